// round 2
// baseline (speedup 1.0000x reference)
#include <cuda_runtime.h>
#include <cstdint>
#include <cstdio>

// ---------------------------------------------------------------------------
// GNNDecoder: h = PReLU(x) @ Wenc^T ; h[mask]=0 ; aggr = segsum(h[src]+emb) ;
//             out = relu(aggr@W1^T+b1) @ W2^T + b2
// GEMMs use packed fma.rn.f32x2 (2 FMA/lane/instr on Blackwell).
// ---------------------------------------------------------------------------

#define MAXN 50176   // N=50000 padded

typedef unsigned long long ull;

// Scratch (device globals; no allocation allowed)
__device__ float g_h[MAXN * 128];
__device__ float g_aggr[MAXN * 128];
__device__ float g_t[MAXN * 256];
__device__ float g_embc[18 * 128];   // emb1[t]+emb2[d]; idx 12 = self-loop [4,0]

// ---------------------------------------------------------------------------
__device__ __forceinline__ ull dup2(float x) {
    unsigned int u = __float_as_uint(x);
    ull d;
    asm("mov.b64 %0, {%1, %1};" : "=l"(d) : "r"(u));
    return d;
}
__device__ __forceinline__ void ffma2(ull& d, ull a, ull b) {
    asm("fma.rn.f32x2 %0, %1, %2, %0;" : "+l"(d) : "l"(a), "l"(b));
}
__device__ __forceinline__ float2 unpack2(ull v) {
    float2 f;
    asm("mov.b64 {%0, %1}, %2;" : "=f"(f.x), "=f"(f.y) : "l"(v));
    return f;
}

// ---------------------------------------------------------------------------
__global__ void setup_emb_kernel(const float* __restrict__ emb1,
                                 const float* __restrict__ emb2) {
    int i = threadIdx.x;  // 128 threads
    #pragma unroll
    for (int t = 0; t < 6; t++)
        #pragma unroll
        for (int d = 0; d < 3; d++)
            g_embc[(t * 3 + d) * 128 + i] = emb1[t * 128 + i] + emb2[d * 128 + i];
}

// ---------------------------------------------------------------------------
// fp32 GEMM via f32x2: C[M,Ntot] = f_out( f_in(A)[M,K] @ B[Ntot,K]^T + bias )
// BM=64, BN=128, K processed in stages of 128. 256 threads, 4x8 micro-tile.
// A tile stored transposed AND duplicated ({a,a} packed b64) in smem so the
// inner loop needs no packing: 4 LDS.128 + 16 FFMA2 per k.
// DUAL: additionally writes C2 = C + addvec.
// ---------------------------------------------------------------------------
template <int K, bool PRELU, bool RELU_OUT, bool BIAS, bool DUAL>
__global__ void __launch_bounds__(256)
gemm_kernel(const float* __restrict__ A, const float* __restrict__ B,
            const float* __restrict__ bias, const float* __restrict__ prelu_pa,
            float* __restrict__ C, float* __restrict__ C2,
            const float* __restrict__ addvec, int M, int Ntot) {
    constexpr int KT = 128;                 // K per stage
    constexpr int NSTAGE = K / KT;
    constexpr int APU = 68;                 // ull per AsT2 row (64 dup'd + 4 pad)
    constexpr int BP  = 136;                // floats per BsT row (128 + 8 pad)
    extern __shared__ float smem[];
    ull*   AsT2 = reinterpret_cast<ull*>(smem);        // [KT][APU] (dup-packed A^T)
    float* BsT  = smem + KT * APU * 2;                 // [KT][BP]  (B^T)

    const int tid = threadIdx.x;
    const int rowbase = blockIdx.x * 64;
    const int colbase = blockIdx.y * 128;

    float pa = 0.0f;
    if (PRELU) pa = *prelu_pa;

    const int tx = tid & 15;   // 16 col-groups of 8 cols
    const int ty = tid >> 4;   // 16 row-groups of 4 rows

    ull acc[4][4];             // [row][colpair], each packs 2 adjacent cols
    #pragma unroll
    for (int r = 0; r < 4; r++)
        #pragma unroll
        for (int c = 0; c < 4; c++) acc[r][c] = 0ULL;

    for (int s = 0; s < NSTAGE; s++) {
        if (s > 0) __syncthreads();

        // ---- load + transpose + duplicate A tile ----
        #pragma unroll
        for (int i = tid; i < 64 * KT / 4; i += 256) {
            int row = i & 63;
            int kq  = i >> 6;
            int gr  = rowbase + row;
            float4 v = make_float4(0.f, 0.f, 0.f, 0.f);
            if (gr < M)
                v = *reinterpret_cast<const float4*>(A + (size_t)gr * K + s * KT + kq * 4);
            if (PRELU) {
                v.x = v.x > 0.f ? v.x : pa * v.x;
                v.y = v.y > 0.f ? v.y : pa * v.y;
                v.z = v.z > 0.f ? v.z : pa * v.z;
                v.w = v.w > 0.f ? v.w : pa * v.w;
            }
            AsT2[(4 * kq + 0) * APU + row] = dup2(v.x);
            AsT2[(4 * kq + 1) * APU + row] = dup2(v.y);
            AsT2[(4 * kq + 2) * APU + row] = dup2(v.z);
            AsT2[(4 * kq + 3) * APU + row] = dup2(v.w);
        }

        // ---- load + transpose B tile ----
        #pragma unroll
        for (int i = tid; i < 128 * KT / 4; i += 256) {
            int row = i & 127;
            int kq  = i >> 7;
            float4 v = *reinterpret_cast<const float4*>(
                B + (size_t)(colbase + row) * K + s * KT + kq * 4);
            BsT[(4 * kq + 0) * BP + row] = v.x;
            BsT[(4 * kq + 1) * BP + row] = v.y;
            BsT[(4 * kq + 2) * BP + row] = v.z;
            BsT[(4 * kq + 3) * BP + row] = v.w;
        }

        __syncthreads();

        const ull* BsTu = reinterpret_cast<const ull*>(BsT);  // row stride 68 ull

        #pragma unroll 8
        for (int k = 0; k < KT; k++) {
            // 4 dup'd A rows (2 x LDS.128)
            ulonglong2 aa = *reinterpret_cast<const ulonglong2*>(&AsT2[k * APU + 4 * ty]);
            ulonglong2 ab = *reinterpret_cast<const ulonglong2*>(&AsT2[k * APU + 4 * ty + 2]);
            // 4 B col-pairs (2 x LDS.128)
            ulonglong2 ba = *reinterpret_cast<const ulonglong2*>(&BsTu[k * (BP / 2) + 4 * tx]);
            ulonglong2 bb = *reinterpret_cast<const ulonglong2*>(&BsTu[k * (BP / 2) + 4 * tx + 2]);

            ffma2(acc[0][0], aa.x, ba.x); ffma2(acc[0][1], aa.x, ba.y);
            ffma2(acc[0][2], aa.x, bb.x); ffma2(acc[0][3], aa.x, bb.y);
            ffma2(acc[1][0], aa.y, ba.x); ffma2(acc[1][1], aa.y, ba.y);
            ffma2(acc[1][2], aa.y, bb.x); ffma2(acc[1][3], aa.y, bb.y);
            ffma2(acc[2][0], ab.x, ba.x); ffma2(acc[2][1], ab.x, ba.y);
            ffma2(acc[2][2], ab.x, bb.x); ffma2(acc[2][3], ab.x, bb.y);
            ffma2(acc[3][0], ab.y, ba.x); ffma2(acc[3][1], ab.y, ba.y);
            ffma2(acc[3][2], ab.y, bb.x); ffma2(acc[3][3], ab.y, bb.y);
        }
    }

    // ---- epilogue ----
    const int gc = colbase + 8 * tx;
    float bvec[8];
    #pragma unroll
    for (int c = 0; c < 8; c++) bvec[c] = 0.f;
    if (BIAS) {
        float4 t0 = *reinterpret_cast<const float4*>(bias + gc);
        float4 t1 = *reinterpret_cast<const float4*>(bias + gc + 4);
        bvec[0] = t0.x; bvec[1] = t0.y; bvec[2] = t0.z; bvec[3] = t0.w;
        bvec[4] = t1.x; bvec[5] = t1.y; bvec[6] = t1.z; bvec[7] = t1.w;
    }
    float avec[8];
    if (DUAL) {
        float4 t0 = *reinterpret_cast<const float4*>(addvec + gc);
        float4 t1 = *reinterpret_cast<const float4*>(addvec + gc + 4);
        avec[0] = t0.x; avec[1] = t0.y; avec[2] = t0.z; avec[3] = t0.w;
        avec[4] = t1.x; avec[5] = t1.y; avec[6] = t1.z; avec[7] = t1.w;
    }

    #pragma unroll
    for (int r = 0; r < 4; r++) {
        int gr = rowbase + 4 * ty + r;
        if (gr >= M) continue;
        float o[8];
        #pragma unroll
        for (int c = 0; c < 4; c++) {
            float2 f = unpack2(acc[r][c]);
            o[2 * c]     = f.x;
            o[2 * c + 1] = f.y;
        }
        #pragma unroll
        for (int c = 0; c < 8; c++) {
            float v = o[c];
            if (BIAS) v += bvec[c];
            if (RELU_OUT) v = v > 0.f ? v : 0.f;
            o[c] = v;
        }
        float* cp = C + (size_t)gr * Ntot + gc;
        *reinterpret_cast<float4*>(cp)     = make_float4(o[0], o[1], o[2], o[3]);
        *reinterpret_cast<float4*>(cp + 4) = make_float4(o[4], o[5], o[6], o[7]);
        if (DUAL) {
            float* cp2 = C2 + (size_t)gr * Ntot + gc;
            *reinterpret_cast<float4*>(cp2)     = make_float4(o[0] + avec[0], o[1] + avec[1],
                                                              o[2] + avec[2], o[3] + avec[3]);
            *reinterpret_cast<float4*>(cp2 + 4) = make_float4(o[4] + avec[4], o[5] + avec[5],
                                                              o[6] + avec[6], o[7] + avec[7]);
        }
    }
}

// ---------------------------------------------------------------------------
// Mask fix: h[m] = 0 ; aggr[m] = selfc (= embc[12])
// ---------------------------------------------------------------------------
__global__ void mask_kernel(const int* __restrict__ mask, int Mm) {
    int g = blockIdx.x * blockDim.x + threadIdx.x;
    int i = g >> 5;
    int lane = g & 31;
    if (i >= Mm) return;
    int row = __ldg(mask + i);
    *reinterpret_cast<float4*>(g_h + (size_t)row * 128 + lane * 4) =
        make_float4(0.f, 0.f, 0.f, 0.f);
    *reinterpret_cast<float4*>(g_aggr + (size_t)row * 128 + lane * 4) =
        *reinterpret_cast<const float4*>(g_embc + 12 * 128 + lane * 4);
}

// ---------------------------------------------------------------------------
// Edge scatter: one warp per edge. aggr[dst] += h[src] + embc[a0*3+a1]
// ---------------------------------------------------------------------------
__global__ void scatter_kernel(const int* __restrict__ ei,
                               const int* __restrict__ ea, int E) {
    int g = blockIdx.x * blockDim.x + threadIdx.x;
    int e = g >> 5;
    int lane = g & 31;
    if (e >= E) return;
    int src = __ldg(ei + e);
    int dst = __ldg(ei + E + e);
    int a0  = __ldg(ea + 2 * e);
    int a1  = __ldg(ea + 2 * e + 1);

    float4 hv = *reinterpret_cast<const float4*>(g_h + (size_t)src * 128 + lane * 4);
    float4 ev = *reinterpret_cast<const float4*>(g_embc + (a0 * 3 + a1) * 128 + lane * 4);
    float4 m = make_float4(hv.x + ev.x, hv.y + ev.y, hv.z + ev.z, hv.w + ev.w);

    float* p = g_aggr + (size_t)dst * 128 + lane * 4;
    asm volatile("red.global.add.v4.f32 [%0], {%1, %2, %3, %4};"
                 :: "l"(p), "f"(m.x), "f"(m.y), "f"(m.z), "f"(m.w)
                 : "memory");
}

// ---------------------------------------------------------------------------
// Host launch
// ---------------------------------------------------------------------------
extern "C" void kernel_launch(void* const* d_in, const int* in_sizes, int n_in,
                              void* d_out, int out_size) {
    const float* x    = (const float*)d_in[0];
    const int*   ei   = (const int*)d_in[1];
    const int*   ea   = (const int*)d_in[2];
    const int*   mask = (const int*)d_in[3];
    const float* pa   = (const float*)d_in[4];
    const float* Wenc = (const float*)d_in[5];
    const float* W1   = (const float*)d_in[6];
    const float* b1   = (const float*)d_in[7];
    const float* W2   = (const float*)d_in[8];
    const float* b2   = (const float*)d_in[9];
    const float* emb1 = (const float*)d_in[10];
    const float* emb2 = (const float*)d_in[11];

    int N  = in_sizes[0] / 128;
    int E  = in_sizes[1] / 2;
    int Mm = in_sizes[3];
    float* out = (float*)d_out;

    float *h, *aggr, *t, *embc;
    cudaGetSymbolAddress((void**)&h,    g_h);
    cudaGetSymbolAddress((void**)&aggr, g_aggr);
    cudaGetSymbolAddress((void**)&t,    g_t);
    cudaGetSymbolAddress((void**)&embc, g_embc);

    // smem per block: AsT2 (128*68 ull) + BsT (128*136 f) = 69632 + 69632
    constexpr int SMEM = 128 * 68 * 8 + 128 * 136 * 4;  // 139264 B
    cudaFuncSetAttribute(gemm_kernel<128, true,  false, false, true>,
                         cudaFuncAttributeMaxDynamicSharedMemorySize, SMEM);
    cudaFuncSetAttribute(gemm_kernel<128, false, true,  true,  false>,
                         cudaFuncAttributeMaxDynamicSharedMemorySize, SMEM);
    cudaFuncSetAttribute(gemm_kernel<256, false, false, true,  false>,
                         cudaFuncAttributeMaxDynamicSharedMemorySize, SMEM);

    // 1) edge-embedding combos
    setup_emb_kernel<<<1, 128>>>(emb1, emb2);

    // 2) G1: h = PReLU(x) @ Wenc^T ; aggr = h + selfc (self-loop init)
    dim3 g1((N + 63) / 64, 1);
    gemm_kernel<128, true, false, false, true><<<g1, 256, SMEM>>>(
        x, Wenc, nullptr, pa, h, aggr, embc + 12 * 128, N, 128);

    // 3) mask: h[m]=0, aggr[m]=selfc
    mask_kernel<<<(Mm * 32 + 255) / 256, 256>>>(mask, Mm);

    // 4) edge scatter (atomic accumulate into aggr)
    long long nthr = (long long)E * 32;
    scatter_kernel<<<(unsigned)((nthr + 255) / 256), 256>>>(ei, ea, E);

    // 5) G2: t = relu(aggr @ W1^T + b1)   [N,128] x [256,128]^T
    dim3 g2((N + 63) / 64, 2);
    gemm_kernel<128, false, true, true, false><<<g2, 256, SMEM>>>(
        aggr, W1, b1, nullptr, t, nullptr, nullptr, N, 256);

    // 6) G3: out = t @ W2^T + b2          [N,256] x [128,256]^T
    dim3 g3((N + 63) / 64, 1);
    gemm_kernel<256, false, false, true, false><<<g3, 256, SMEM>>>(
        t, W2, b2, nullptr, out, nullptr, nullptr, N, 128);
}

// round 4
// speedup vs baseline: 2.4658x; 2.4658x over previous
#include <cuda_runtime.h>
#include <cuda_bf16.h>
#include <cstdint>

typedef unsigned int u32;

#define MAXN 50176   // N=50000 padded to 128

// ---------------------------------------------------------------------------
// Device-global scratch (no allocation allowed)
// ---------------------------------------------------------------------------
__device__ float g_h[MAXN * 128];
__device__ float g_aggr[MAXN * 128];
__device__ float g_t[MAXN * 256];
__device__ float g_embc[18 * 128];   // emb1[t]+emb2[d]; idx 12 = self-loop
// Pre-split weights, natural row-major [out][K]:
// Wenc @0 (16384), W1 @16384 (32768), W2 @49152 (32768)
__device__ __nv_bfloat16 g_Wh[81920];
__device__ __nv_bfloat16 g_Wl[81920];

// ---------------------------------------------------------------------------
// Helpers
// ---------------------------------------------------------------------------
__device__ __forceinline__ u32 smem_u32(const void* p) {
    u32 a;
    asm("{ .reg .u64 t; cvta.to.shared.u64 t, %1; cvt.u32.u64 %0, t; }"
        : "=r"(a) : "l"(p));
    return a;
}

__device__ __forceinline__ void ldsm4(u32& r0, u32& r1, u32& r2, u32& r3, u32 addr) {
    asm volatile("ldmatrix.sync.aligned.m8n8.x4.shared.b16 {%0,%1,%2,%3}, [%4];"
                 : "=r"(r0), "=r"(r1), "=r"(r2), "=r"(r3) : "r"(addr));
}

__device__ __forceinline__ void mma16816(float* c, const u32* a, u32 b0, u32 b1) {
    asm volatile(
        "mma.sync.aligned.m16n8k16.row.col.f32.bf16.bf16.f32 "
        "{%0,%1,%2,%3}, {%4,%5,%6,%7}, {%8,%9}, {%0,%1,%2,%3};"
        : "+f"(c[0]), "+f"(c[1]), "+f"(c[2]), "+f"(c[3])
        : "r"(a[0]), "r"(a[1]), "r"(a[2]), "r"(a[3]), "r"(b0), "r"(b1));
}

__device__ __forceinline__ u32 pack_bf(__nv_bfloat16 a, __nv_bfloat16 b) {
    return (u32)__bfloat16_as_ushort(a) | ((u32)__bfloat16_as_ushort(b) << 16);
}

__device__ __forceinline__ void split4(float4 v, uint2& hi, uint2& lo) {
    __nv_bfloat16 h0 = __float2bfloat16(v.x), h1 = __float2bfloat16(v.y);
    __nv_bfloat16 h2 = __float2bfloat16(v.z), h3 = __float2bfloat16(v.w);
    __nv_bfloat16 l0 = __float2bfloat16(v.x - __bfloat162float(h0));
    __nv_bfloat16 l1 = __float2bfloat16(v.y - __bfloat162float(h1));
    __nv_bfloat16 l2 = __float2bfloat16(v.z - __bfloat162float(h2));
    __nv_bfloat16 l3 = __float2bfloat16(v.w - __bfloat162float(h3));
    hi = make_uint2(pack_bf(h0, h1), pack_bf(h2, h3));
    lo = make_uint2(pack_bf(l0, l1), pack_bf(l2, l3));
}

// ---------------------------------------------------------------------------
// Setup kernels
// ---------------------------------------------------------------------------
__global__ void setup_emb_kernel(const float* __restrict__ emb1,
                                 const float* __restrict__ emb2) {
    int i = threadIdx.x;  // 128 threads
    #pragma unroll
    for (int t = 0; t < 6; t++)
        #pragma unroll
        for (int d = 0; d < 3; d++)
            g_embc[(t * 3 + d) * 128 + i] = emb1[t * 128 + i] + emb2[d * 128 + i];
}

// Split fp32 weights -> bf16 hi/lo, same (linear) layout.
__global__ void conv_kernel(const float* __restrict__ W, int n4,
                            __nv_bfloat16* __restrict__ dh,
                            __nv_bfloat16* __restrict__ dl) {
    int idx = blockIdx.x * blockDim.x + threadIdx.x;
    if (idx >= n4) return;
    float4 v = reinterpret_cast<const float4*>(W)[idx];
    uint2 hi, lo;
    split4(v, hi, lo);
    reinterpret_cast<uint2*>(dh)[idx] = hi;
    reinterpret_cast<uint2*>(dl)[idx] = lo;
}

// ---------------------------------------------------------------------------
// HMMA bf16 split GEMM: C[M,Ntot] = f(A[M,K] @ B[Ntot,K]^T + bias)
// CTA 128x128, 256 threads (8 warps, 2x4), warp tile 64x32, k16 steps.
// D = Ah@Bh + Ah@Bl + Al@Bh (fp32 accum in regs).
// ---------------------------------------------------------------------------
template <int KST, bool PRELU, bool RELU, bool BIAS, bool DUAL>
__global__ void __launch_bounds__(256)
mma_gemm(const float* __restrict__ A,
         const __nv_bfloat16* __restrict__ Bh, const __nv_bfloat16* __restrict__ Bl,
         const float* __restrict__ bias, const float* __restrict__ prelu_pa,
         float* __restrict__ C, float* __restrict__ C2,
         const float* __restrict__ addvec, int M, int Ntot) {
    constexpr int RS = 272;               // smem row stride bytes (128 bf16 + 8 pad)
    constexpr int BUF = 128 * RS;         // 34816 B per tile buffer
    extern __shared__ __align__(16) char smem[];
    char* sAh = smem;
    char* sAl = smem + BUF;
    char* sBh = smem + 2 * BUF;
    char* sBl = smem + 3 * BUF;

    const int tid = threadIdx.x;
    const int wid = tid >> 5, lid = tid & 31;
    const int wm = wid >> 2;              // 0..1 (64-row band)
    const int wn = wid & 3;               // 0..3 (32-col band)
    const int rowbase = blockIdx.x * 128;
    const int colbase = blockIdx.y * 128;
    const int K = KST * 128;

    const u32 aAh = smem_u32(sAh), aAl = smem_u32(sAl);
    const u32 aBh = smem_u32(sBh), aBl = smem_u32(sBl);

    float pa = PRELU ? *prelu_pa : 0.f;

    float acc[4][4][4];
    #pragma unroll
    for (int i = 0; i < 4; i++)
        #pragma unroll
        for (int j = 0; j < 4; j++)
            #pragma unroll
            for (int q = 0; q < 4; q++) acc[i][j][q] = 0.f;

    for (int s = 0; s < KST; s++) {
        if (s > 0) __syncthreads();

        // ---- A tile: load fp32, (prelu), split hi/lo into padded smem ----
        #pragma unroll
        for (int i = 0; i < 16; i++) {
            int idx = i * 256 + tid;      // 4096 float4
            int row = idx >> 5;
            int c4 = idx & 31;
            int grow = rowbase + row;
            float4 v = make_float4(0.f, 0.f, 0.f, 0.f);
            if (grow < M)
                v = *reinterpret_cast<const float4*>(A + (size_t)grow * K + s * 128 + c4 * 4);
            if (PRELU) {
                v.x = v.x > 0.f ? v.x : pa * v.x;
                v.y = v.y > 0.f ? v.y : pa * v.y;
                v.z = v.z > 0.f ? v.z : pa * v.z;
                v.w = v.w > 0.f ? v.w : pa * v.w;
            }
            uint2 hi, lo;
            split4(v, hi, lo);
            *reinterpret_cast<uint2*>(sAh + row * RS + c4 * 8) = hi;
            *reinterpret_cast<uint2*>(sAl + row * RS + c4 * 8) = lo;
        }

        // ---- B tile: bf16 copy into padded smem ----
        #pragma unroll
        for (int i = 0; i < 16; i++) {
            int idx = i * 256 + tid;      // 4096 uint2 (4 bf16 each)
            int row = idx >> 5;
            int j = idx & 31;
            const __nv_bfloat16* srh = Bh + (size_t)(colbase + row) * K + s * 128;
            const __nv_bfloat16* srl = Bl + (size_t)(colbase + row) * K + s * 128;
            *reinterpret_cast<uint2*>(sBh + row * RS + j * 8) =
                reinterpret_cast<const uint2*>(srh)[j];
            *reinterpret_cast<uint2*>(sBl + row * RS + j * 8) =
                reinterpret_cast<const uint2*>(srl)[j];
        }

        __syncthreads();

        // ---- compute: 8 k16 steps ----
        #pragma unroll
        for (int k = 0; k < 8; k++) {
            u32 bh[2][4], bl[2][4];
            #pragma unroll
            for (int nj = 0; nj < 2; nj++) {
                int row = wn * 32 + nj * 16 + (lid & 7) + ((lid >> 4) << 3);
                int colb = k * 32 + ((lid >> 3) & 1) * 16;
                ldsm4(bh[nj][0], bh[nj][1], bh[nj][2], bh[nj][3], aBh + row * RS + colb);
                ldsm4(bl[nj][0], bl[nj][1], bl[nj][2], bl[nj][3], aBl + row * RS + colb);
            }
            #pragma unroll
            for (int mi = 0; mi < 4; mi++) {
                int arow = wm * 64 + mi * 16 + (lid & 15);
                int acolb = k * 32 + ((lid >> 4) << 4);
                u32 ah[4], al[4];
                ldsm4(ah[0], ah[1], ah[2], ah[3], aAh + arow * RS + acolb);
                ldsm4(al[0], al[1], al[2], al[3], aAl + arow * RS + acolb);
                #pragma unroll
                for (int n8 = 0; n8 < 4; n8++) {
                    int nj = n8 >> 1, p = (n8 & 1) * 2;
                    mma16816(acc[mi][n8], ah, bh[nj][p], bh[nj][p + 1]);
                    mma16816(acc[mi][n8], ah, bl[nj][p], bl[nj][p + 1]);
                    mma16816(acc[mi][n8], al, bh[nj][p], bh[nj][p + 1]);
                }
            }
        }
    }

    // ---- epilogue ----
    const int g = lid >> 2, t = lid & 3;
    #pragma unroll
    for (int mi = 0; mi < 4; mi++) {
        #pragma unroll
        for (int n8 = 0; n8 < 4; n8++) {
            int gr0 = rowbase + wm * 64 + mi * 16 + g;
            int gr1 = gr0 + 8;
            int gc  = colbase + wn * 32 + n8 * 8 + 2 * t;
            float c0 = acc[mi][n8][0], c1 = acc[mi][n8][1];
            float c2 = acc[mi][n8][2], c3 = acc[mi][n8][3];
            if (BIAS) {
                float bb0 = __ldg(bias + gc), bb1 = __ldg(bias + gc + 1);
                c0 += bb0; c1 += bb1; c2 += bb0; c3 += bb1;
            }
            if (RELU) {
                c0 = fmaxf(c0, 0.f); c1 = fmaxf(c1, 0.f);
                c2 = fmaxf(c2, 0.f); c3 = fmaxf(c3, 0.f);
            }
            float av0 = 0.f, av1 = 0.f;
            if (DUAL) { av0 = __ldg(addvec + gc); av1 = __ldg(addvec + gc + 1); }
            if (gr0 < M) {
                *reinterpret_cast<float2*>(C + (size_t)gr0 * Ntot + gc) = make_float2(c0, c1);
                if (DUAL)
                    *reinterpret_cast<float2*>(C2 + (size_t)gr0 * Ntot + gc) =
                        make_float2(c0 + av0, c1 + av1);
            }
            if (gr1 < M) {
                *reinterpret_cast<float2*>(C + (size_t)gr1 * Ntot + gc) = make_float2(c2, c3);
                if (DUAL)
                    *reinterpret_cast<float2*>(C2 + (size_t)gr1 * Ntot + gc) =
                        make_float2(c2 + av0, c3 + av1);
            }
        }
    }
}

// ---------------------------------------------------------------------------
// Mask fix: h[m] = 0 ; aggr[m] = selfc (= embc[12])
// ---------------------------------------------------------------------------
__global__ void mask_kernel(const int* __restrict__ mask, int Mm) {
    int g = blockIdx.x * blockDim.x + threadIdx.x;
    int i = g >> 5;
    int lane = g & 31;
    if (i >= Mm) return;
    int row = __ldg(mask + i);
    *reinterpret_cast<float4*>(g_h + (size_t)row * 128 + lane * 4) =
        make_float4(0.f, 0.f, 0.f, 0.f);
    *reinterpret_cast<float4*>(g_aggr + (size_t)row * 128 + lane * 4) =
        *reinterpret_cast<const float4*>(g_embc + 12 * 128 + lane * 4);
}

// ---------------------------------------------------------------------------
// Edge scatter: one warp per edge. aggr[dst] += h[src] + embc[a0*3+a1]
// ---------------------------------------------------------------------------
__global__ void scatter_kernel(const int* __restrict__ ei,
                               const int* __restrict__ ea, int E) {
    int g = blockIdx.x * blockDim.x + threadIdx.x;
    int e = g >> 5;
    int lane = g & 31;
    if (e >= E) return;
    int src = __ldg(ei + e);
    int dst = __ldg(ei + E + e);
    int a0  = __ldg(ea + 2 * e);
    int a1  = __ldg(ea + 2 * e + 1);

    float4 hv = *reinterpret_cast<const float4*>(g_h + (size_t)src * 128 + lane * 4);
    float4 ev = *reinterpret_cast<const float4*>(g_embc + (a0 * 3 + a1) * 128 + lane * 4);
    float4 m = make_float4(hv.x + ev.x, hv.y + ev.y, hv.z + ev.z, hv.w + ev.w);

    float* p = g_aggr + (size_t)dst * 128 + lane * 4;
    asm volatile("red.global.add.v4.f32 [%0], {%1, %2, %3, %4};"
                 :: "l"(p), "f"(m.x), "f"(m.y), "f"(m.z), "f"(m.w)
                 : "memory");
}

// ---------------------------------------------------------------------------
// Host launch
// ---------------------------------------------------------------------------
extern "C" void kernel_launch(void* const* d_in, const int* in_sizes, int n_in,
                              void* d_out, int out_size) {
    const float* x    = (const float*)d_in[0];
    const int*   ei   = (const int*)d_in[1];
    const int*   ea   = (const int*)d_in[2];
    const int*   mask = (const int*)d_in[3];
    const float* pa   = (const float*)d_in[4];
    const float* Wenc = (const float*)d_in[5];
    const float* W1   = (const float*)d_in[6];
    const float* b1   = (const float*)d_in[7];
    const float* W2   = (const float*)d_in[8];
    const float* b2   = (const float*)d_in[9];
    const float* emb1 = (const float*)d_in[10];
    const float* emb2 = (const float*)d_in[11];

    int N  = in_sizes[0] / 128;
    int E  = in_sizes[1] / 2;
    int Mm = in_sizes[3];
    float* out = (float*)d_out;

    float *h, *aggr, *t, *embc;
    __nv_bfloat16 *wh, *wl;
    cudaGetSymbolAddress((void**)&h,    g_h);
    cudaGetSymbolAddress((void**)&aggr, g_aggr);
    cudaGetSymbolAddress((void**)&t,    g_t);
    cudaGetSymbolAddress((void**)&embc, g_embc);
    cudaGetSymbolAddress((void**)&wh,   g_Wh);
    cudaGetSymbolAddress((void**)&wl,   g_Wl);

    constexpr int SMEMSZ = 4 * 128 * 272;   // 139264 B
    cudaFuncSetAttribute(mma_gemm<1, true,  false, false, true>,
                         cudaFuncAttributeMaxDynamicSharedMemorySize, SMEMSZ);
    cudaFuncSetAttribute(mma_gemm<1, false, true,  true,  false>,
                         cudaFuncAttributeMaxDynamicSharedMemorySize, SMEMSZ);
    cudaFuncSetAttribute(mma_gemm<2, false, false, true,  false>,
                         cudaFuncAttributeMaxDynamicSharedMemorySize, SMEMSZ);

    // 0) setup: edge-embedding combos + weight splits
    setup_emb_kernel<<<1, 128>>>(emb1, emb2);
    conv_kernel<<<16, 256>>>(Wenc, 4096, wh,          wl);
    conv_kernel<<<32, 256>>>(W1,   8192, wh + 16384,  wl + 16384);
    conv_kernel<<<32, 256>>>(W2,   8192, wh + 49152,  wl + 49152);

    int gx = (N + 127) / 128;

    // 1) G1: h = PReLU(x) @ Wenc^T ; aggr = h + selfc
    mma_gemm<1, true, false, false, true><<<dim3(gx, 1), 256, SMEMSZ>>>(
        x, wh, wl, nullptr, pa, h, aggr, embc + 12 * 128, N, 128);

    // 2) mask: h[m]=0, aggr[m]=selfc
    mask_kernel<<<(Mm * 32 + 255) / 256, 256>>>(mask, Mm);

    // 3) edge scatter
    long long nthr = (long long)E * 32;
    scatter_kernel<<<(unsigned)((nthr + 255) / 256), 256>>>(ei, ea, E);

    // 4) G2: t = relu(aggr @ W1^T + b1)   [N,128] x [256,128]^T
    mma_gemm<1, false, true, true, false><<<dim3(gx, 2), 256, SMEMSZ>>>(
        aggr, wh + 16384, wl + 16384, b1, nullptr, t, nullptr, nullptr, N, 256);

    // 5) G3: out = t @ W2^T + b2          [N,256] x [128,256]^T
    mma_gemm<2, false, false, true, false><<<dim3(gx, 1), 256, SMEMSZ>>>(
        t, wh + 49152, wl + 49152, b2, nullptr, out, nullptr, nullptr, N, 128);
}